// round 15
// baseline (speedup 1.0000x reference)
#include <cuda_runtime.h>
#include <cuda_fp16.h>
#include <cstdint>

#define H 512
#define W 512
#define C 32
#define BATCH 4

// ---- device scratch (no allocation) ----
__device__ float g_x[BATCH * H * W];  // intermediate 1-channel map

// ---- smem layout (dynamic) ----
// A ring: 6 slots, each [x:130][ci:32] fp16, x-stride 80B (conflict-free ldsm)
#define A_XSTR     80
#define A_SLOT     (130 * A_XSTR)           // 10400
#define OFF_WB     (6 * A_SLOT)             // 62400
#define WB_STRIDE  592                      // 288*2 (hi only) + 16 pad
#define OFF_BIAS   (OFF_WB + C * WB_STRIDE) // 81344
#define OFF_W1     (OFF_BIAS + 128)
#define OFF_B1     (OFF_W1 + 128)
#define SMEM_TOTAL (OFF_B1 + 128)

__device__ __forceinline__ uint32_t smem_u32(const void* p) {
    uint32_t a;
    asm("{ .reg .u64 t; cvta.to.shared.u64 t, %1; cvt.u32.u64 %0, t; }" : "=r"(a) : "l"(p));
    return a;
}

__device__ __forceinline__ void ldsm_x4(uint32_t addr, uint32_t& r0, uint32_t& r1,
                                        uint32_t& r2, uint32_t& r3) {
    asm volatile("ldmatrix.sync.aligned.m8n8.x4.shared.b16 {%0,%1,%2,%3}, [%4];"
                 : "=r"(r0), "=r"(r1), "=r"(r2), "=r"(r3) : "r"(addr));
}

__device__ __forceinline__ void mma_f16(float* c, const uint32_t* a, uint32_t b0,
                                        uint32_t b1) {
    asm volatile(
        "mma.sync.aligned.m16n8k16.row.col.f32.f16.f16.f32 "
        "{%0,%1,%2,%3}, {%4,%5,%6,%7}, {%8,%9}, {%0,%1,%2,%3};"
        : "+f"(c[0]), "+f"(c[1]), "+f"(c[2]), "+f"(c[3])
        : "r"(a[0]), "r"(a[1]), "r"(a[2]), "r"(a[3]), "r"(b0), "r"(b1));
}

// silu via tanh.approx: v*sigmoid(v) = 0.5v + 0.5v*tanh(v/2)  (1 MUFU)
__device__ __forceinline__ float silu_fast(float v) {
    float th;
    asm("tanh.approx.f32 %0, %1;" : "=f"(th) : "f"(0.5f * v));
    float hv = 0.5f * v;
    return fmaf(hv, th, hv);
}

// LDG one input row into registers (17 per thread, unrolled -> high MLP)
__device__ __forceinline__ void ldg_row(const float* __restrict__ cen, int b, int yin,
                                        int x0, int t, float* va) {
    const bool ok = (unsigned)yin < (unsigned)H;
#pragma unroll
    for (int i = 0; i < 17; i++) {
        int e = t + i * 256;
        float v = 0.f;
        if (e < 4160 && ok) {
            int ci = e / 130;
            int x = e - ci * 130;
            int gx = x0 - 1 + x;
            if ((unsigned)gx < (unsigned)W)
                v = __ldg(&cen[(((size_t)b * C + ci) * H + yin) * W + gx]);
        }
        va[i] = v;
    }
}

// convert + store one row into its ring slot
__device__ __forceinline__ void sts_row(char* smem, int yin, int t, const float* va) {
    char* Ab = smem + ((yin + 6) % 6) * A_SLOT;
#pragma unroll
    for (int i = 0; i < 17; i++) {
        int e = t + i * 256;
        if (e < 4160) {
            int ci = e / 130;
            int x = e - ci * 130;
            *reinterpret_cast<__half*>(Ab + x * A_XSTR + ci * 2) = __float2half(va[i]);
        }
    }
}

// ---- K1: implicit-GEMM conv3x3 (fp16 mma.sync) + BN + SiLU + 1x1 ----
__global__ __launch_bounds__(256, 2) void stage1_kernel(
    const float* __restrict__ cen, const float* __restrict__ w_conv,
    const float* __restrict__ gamma, const float* __restrict__ beta,
    const float* __restrict__ mean, const float* __restrict__ var,
    const float* __restrict__ w1x1, const float* __restrict__ b1x1) {
    extern __shared__ __align__(128) char smem[];
    float* biasS = (float*)(smem + OFF_BIAS);
    float* w1S = (float*)(smem + OFF_W1);
    float* b1S = (float*)(smem + OFF_B1);

    const int t = threadIdx.x;
    const int lane = t & 31;
    const int wrp = t >> 5;
    const int x0 = blockIdx.x * 128;
    const int y0 = blockIdx.y * 16;
    const int b = blockIdx.z;
    const uint32_t sbase = smem_u32(smem);

    // weights (BN-folded, fp16) -> WB[co][pos*32+ci]
    for (int i = t; i < C * C * 9; i += 256) {
        int co = i / 288;
        int rem = i - co * 288;
        int ci = rem / 9;
        int pos = rem - ci * 9;
        float inv = __ldg(&gamma[co]) * rsqrtf(__ldg(&var[co]) + 1e-5f);
        float w = __ldg(&w_conv[i]) * inv;
        char* p = smem + OFF_WB + co * WB_STRIDE + (pos * 32 + ci) * 2;
        *reinterpret_cast<__half*>(p) = __float2half(w);
    }
    if (t < C) {
        float inv = __ldg(&gamma[t]) * rsqrtf(__ldg(&var[t]) + 1e-5f);
        biasS[t] = __ldg(&beta[t]) - __ldg(&mean[t]) * inv;
        w1S[t] = __ldg(&w1x1[t]);
    }
    if (t == 0) b1S[0] = __ldg(b1x1);

    // preload rows y0-1 .. y0+2
    {
        float va[17];
#pragma unroll
        for (int rr = 0; rr < 4; rr++) {
            ldg_row(cen, b, y0 - 1 + rr, x0, t, va);
            sts_row(smem, y0 - 1 + rr, t, va);
        }
    }
    __syncthreads();

    // per-warp geometry: row r = wrp>>2, px0 = (wrp&3)*32
    const int r = wrp >> 2;
    const int px0 = (wrp & 3) * 32;

    // lane-invariant ldmatrix address pieces
    const uint32_t aLane = (uint32_t)((px0 + (lane & 15)) * A_XSTR + ((lane & 16) ? 16 : 0));
    const uint32_t bLane = sbase + OFF_WB +
                           (uint32_t)(((lane & 7) + ((lane & 16) ? 8 : 0)) * WB_STRIDE +
                                      ((lane & 8) ? 16 : 0));
    const int g = lane >> 2;
    const int tid4 = lane & 3;

    for (int y = y0; y < y0 + 16; y += 2) {
        // prefetch rows y+3, y+4 into registers (hidden under MMA)
        float va[17], vb[17];
        ldg_row(cen, b, y + 3, x0, t, va);
        ldg_row(cen, b, y + 4, x0, t, vb);

        float Cfr[2][4][4];
#pragma unroll
        for (int mt = 0; mt < 2; mt++)
#pragma unroll
            for (int nt = 0; nt < 4; nt++)
#pragma unroll
                for (int q = 0; q < 4; q++) Cfr[mt][nt][q] = 0.f;

        const int yr = y + r;
#pragma unroll
        for (int kh = 0; kh < 3; kh++) {
            const uint32_t aRing = sbase + ((yr - 1 + kh + 6) % 6) * A_SLOT + aLane;
#pragma unroll
            for (int kw = 0; kw < 3; kw++) {
                const int pos = kh * 3 + kw;
                const uint32_t aBase = aRing + kw * A_XSTR;
                const uint32_t bBase = bLane + pos * 64;
#pragma unroll
                for (int cih = 0; cih < 2; cih++) {
                    uint32_t Ah[2][4], Bh[8];
                    const uint32_t aOff = aBase + cih * 32;
#pragma unroll
                    for (int mt = 0; mt < 2; mt++)
                        ldsm_x4(aOff + mt * (16 * A_XSTR), Ah[mt][0], Ah[mt][1],
                                Ah[mt][2], Ah[mt][3]);
                    const uint32_t bOff = bBase + cih * 32;
                    ldsm_x4(bOff, Bh[0], Bh[1], Bh[2], Bh[3]);
                    ldsm_x4(bOff + 16 * WB_STRIDE, Bh[4], Bh[5], Bh[6], Bh[7]);
#pragma unroll
                    for (int mt = 0; mt < 2; mt++)
#pragma unroll
                        for (int nt = 0; nt < 4; nt++)
                            mma_f16(Cfr[mt][nt], Ah[mt], Bh[nt * 2], Bh[nt * 2 + 1]);
                }
            }
        }

        // commit prefetched rows BEFORE the barrier (writes slots y+3,y+4:
        // disjoint from this iter's read slots y-1..y+2 among 6 residues)
        sts_row(smem, y + 3, t, va);
        sts_row(smem, y + 4, t, vb);
        __syncthreads();

        // epilogue AFTER the barrier: bias + SiLU + 1x1 dot, quad-lane reduce
        const float b1v = b1S[0];
#pragma unroll
        for (int mt = 0; mt < 2; mt++) {
            float sA = 0.f, sB = 0.f;
#pragma unroll
            for (int nt = 0; nt < 4; nt++) {
                int co0 = nt * 8 + 2 * tid4;
                float bs0 = biasS[co0], bs1 = biasS[co0 + 1];
                float w10 = w1S[co0], w11 = w1S[co0 + 1];
                float v0 = Cfr[mt][nt][0] + bs0;
                float v1 = Cfr[mt][nt][1] + bs1;
                float v2 = Cfr[mt][nt][2] + bs0;
                float v3 = Cfr[mt][nt][3] + bs1;
                sA = fmaf(w10, silu_fast(v0), sA);
                sA = fmaf(w11, silu_fast(v1), sA);
                sB = fmaf(w10, silu_fast(v2), sB);
                sB = fmaf(w11, silu_fast(v3), sB);
            }
            sA += __shfl_xor_sync(0xFFFFFFFF, sA, 1);
            sA += __shfl_xor_sync(0xFFFFFFFF, sA, 2);
            sB += __shfl_xor_sync(0xFFFFFFFF, sB, 1);
            sB += __shfl_xor_sync(0xFFFFFFFF, sB, 2);
            if (tid4 == 0) {
                int px = px0 + mt * 16;
                float* gp = &g_x[((size_t)b * H + yr) * W + x0 + px];
                gp[g] = sA + b1v;
                gp[g + 8] = sB + b1v;
            }
        }
    }
}

// ---- K2: shifted-difference attention + gate all channels ----
__device__ __forceinline__ float ldx(const float* __restrict__ X, int i, int j) {
    if ((unsigned)i < (unsigned)H && (unsigned)j < (unsigned)W)
        return __ldg(X + i * W + j);
    return 0.f;
}

__global__ __launch_bounds__(128) void stage2_kernel(
    const float* __restrict__ cen, float* __restrict__ out) {
    const int i = blockIdx.x;
    const int b = blockIdx.y;
    const int j0 = threadIdx.x * 4;
    const float* X = g_x + (size_t)b * H * W;

    float4 av;
    float* avp = (float*)&av;
#pragma unroll
    for (int p = 0; p < 4; p++) {
        int j = j0 + p;
        float x0 = X[i * W + j];
        float ms[2];
#pragma unroll
        for (int si = 0; si < 2; si++) {
            int s = si ? 3 : 1;
            float p0 = (x0 - ldx(X, i - s, j - s)) * (x0 - ldx(X, i + s, j + s));
            float p1 = (x0 - ldx(X, i - s, j)) * (x0 - ldx(X, i + s, j));
            float p2 = (x0 - ldx(X, i - s, j + s)) * (x0 - ldx(X, i + s, j - s));
            float p3 = (x0 - ldx(X, i, j - s)) * (x0 - ldx(X, i, j + s));
            ms[si] = fminf(fminf(p0, p1), fminf(p2, p3));
        }
        float att_in = (fmaxf(ms[0], ms[1]) + 0.5f * (ms[0] + ms[1])) * 0.5f;
        float rr = fmaxf(att_in, 0.f);
        avp[p] = 1.f / (1.f + __expf(-rr));
    }

    size_t base = ((size_t)b * C * H + i) * W + j0;
#pragma unroll
    for (int c = 0; c < C; c++) {
        const float4 v = *(const float4*)(cen + base + (size_t)c * H * W);
        float4 o;
        o.x = v.x * av.x;
        o.y = v.y * av.y;
        o.z = v.z * av.z;
        o.w = v.w * av.w;
        *(float4*)(out + base + (size_t)c * H * W) = o;
    }
}

extern "C" void kernel_launch(void* const* d_in, const int* in_sizes, int n_in,
                              void* d_out, int out_size) {
    const float* cen = (const float*)d_in[0];
    const float* w_conv = (const float*)d_in[1];
    const float* gamma = (const float*)d_in[2];
    const float* beta = (const float*)d_in[3];
    const float* mean = (const float*)d_in[4];
    const float* var = (const float*)d_in[5];
    const float* w1x1 = (const float*)d_in[6];
    const float* b1x1 = (const float*)d_in[7];
    float* out = (float*)d_out;

    cudaFuncSetAttribute(stage1_kernel, cudaFuncAttributeMaxDynamicSharedMemorySize,
                         SMEM_TOTAL);

    stage1_kernel<<<dim3(4, 32, BATCH), 256, SMEM_TOTAL>>>(cen, w_conv, gamma, beta,
                                                           mean, var, w1x1, b1x1);
    stage2_kernel<<<dim3(H, BATCH), 128>>>(cen, out);
}

// round 16
// speedup vs baseline: 1.0788x; 1.0788x over previous
#include <cuda_runtime.h>
#include <cuda_fp16.h>
#include <cstdint>

#define H 512
#define W 512
#define C 32
#define BATCH 4

// ---- device scratch (no allocation) ----
__device__ float g_x[BATCH * H * W];  // intermediate 1-channel map

// ---- smem layout (dynamic) ----
// A ring: 6 slots, each [x:130][ci:32] fp16, x-stride 80B (conflict-free ldsm)
#define A_XSTR     80
#define A_SLOT     (130 * A_XSTR)           // 10400
#define OFF_WB     (6 * A_SLOT)             // 62400
#define WB_STRIDE  592                      // 288*2 (hi only) + 16 pad
#define OFF_BIAS   (OFF_WB + C * WB_STRIDE) // 81344
#define OFF_W1     (OFF_BIAS + 128)
#define OFF_B1     (OFF_W1 + 128)
#define SMEM_TOTAL (OFF_B1 + 128)

__device__ __forceinline__ uint32_t smem_u32(const void* p) {
    uint32_t a;
    asm("{ .reg .u64 t; cvta.to.shared.u64 t, %1; cvt.u32.u64 %0, t; }" : "=r"(a) : "l"(p));
    return a;
}

__device__ __forceinline__ void ldsm_x4(uint32_t addr, uint32_t& r0, uint32_t& r1,
                                        uint32_t& r2, uint32_t& r3) {
    asm volatile("ldmatrix.sync.aligned.m8n8.x4.shared.b16 {%0,%1,%2,%3}, [%4];"
                 : "=r"(r0), "=r"(r1), "=r"(r2), "=r"(r3) : "r"(addr));
}

__device__ __forceinline__ void mma_f16(float* c, const uint32_t* a, uint32_t b0,
                                        uint32_t b1) {
    asm volatile(
        "mma.sync.aligned.m16n8k16.row.col.f32.f16.f16.f32 "
        "{%0,%1,%2,%3}, {%4,%5,%6,%7}, {%8,%9}, {%0,%1,%2,%3};"
        : "+f"(c[0]), "+f"(c[1]), "+f"(c[2]), "+f"(c[3])
        : "r"(a[0]), "r"(a[1]), "r"(a[2]), "r"(a[3]), "r"(b0), "r"(b1));
}

// silu via tanh.approx: v*sigmoid(v) = 0.5v + 0.5v*tanh(v/2)  (1 MUFU)
__device__ __forceinline__ float silu_fast(float v) {
    float th;
    asm("tanh.approx.f32 %0, %1;" : "=f"(th) : "f"(0.5f * v));
    float hv = 0.5f * v;
    return fmaf(hv, th, hv);
}

// LDG one input row into registers (17 per thread, unrolled -> high MLP)
__device__ __forceinline__ void ldg_row(const float* __restrict__ cen, int b, int yin,
                                        int x0, int t, float* va) {
    const bool ok = (unsigned)yin < (unsigned)H;
#pragma unroll
    for (int i = 0; i < 17; i++) {
        int e = t + i * 256;
        float v = 0.f;
        if (e < 4160 && ok) {
            int ci = e / 130;
            int x = e - ci * 130;
            int gx = x0 - 1 + x;
            if ((unsigned)gx < (unsigned)W)
                v = __ldg(&cen[(((size_t)b * C + ci) * H + yin) * W + gx]);
        }
        va[i] = v;
    }
}

// convert + store one row into its ring slot
__device__ __forceinline__ void sts_row(char* smem, int yin, int t, const float* va) {
    char* Ab = smem + ((yin + 6) % 6) * A_SLOT;
#pragma unroll
    for (int i = 0; i < 17; i++) {
        int e = t + i * 256;
        if (e < 4160) {
            int ci = e / 130;
            int x = e - ci * 130;
            *reinterpret_cast<__half*>(Ab + x * A_XSTR + ci * 2) = __float2half(va[i]);
        }
    }
}

// ---- K1: implicit-GEMM conv3x3 (fp16 mma.sync) + BN + SiLU + 1x1 ----
__global__ __launch_bounds__(256, 2) void stage1_kernel(
    const float* __restrict__ cen, const float* __restrict__ w_conv,
    const float* __restrict__ gamma, const float* __restrict__ beta,
    const float* __restrict__ mean, const float* __restrict__ var,
    const float* __restrict__ w1x1, const float* __restrict__ b1x1) {
    extern __shared__ __align__(128) char smem[];
    float* biasS = (float*)(smem + OFF_BIAS);
    float* w1S = (float*)(smem + OFF_W1);
    float* b1S = (float*)(smem + OFF_B1);

    const int t = threadIdx.x;
    const int lane = t & 31;
    const int wrp = t >> 5;
    const int x0 = blockIdx.x * 128;
    const int y0 = blockIdx.y * 32;
    const int b = blockIdx.z;
    const uint32_t sbase = smem_u32(smem);

    // weights (BN-folded, fp16) -> WB[co][pos*32+ci]
    for (int i = t; i < C * C * 9; i += 256) {
        int co = i / 288;
        int rem = i - co * 288;
        int ci = rem / 9;
        int pos = rem - ci * 9;
        float inv = __ldg(&gamma[co]) * rsqrtf(__ldg(&var[co]) + 1e-5f);
        float w = __ldg(&w_conv[i]) * inv;
        char* p = smem + OFF_WB + co * WB_STRIDE + (pos * 32 + ci) * 2;
        *reinterpret_cast<__half*>(p) = __float2half(w);
    }
    if (t < C) {
        float inv = __ldg(&gamma[t]) * rsqrtf(__ldg(&var[t]) + 1e-5f);
        biasS[t] = __ldg(&beta[t]) - __ldg(&mean[t]) * inv;
        w1S[t] = __ldg(&w1x1[t]);
    }
    if (t == 0) b1S[0] = __ldg(b1x1);

    // preload rows y0-1 .. y0+2
    {
        float va[17];
#pragma unroll
        for (int rr = 0; rr < 4; rr++) {
            ldg_row(cen, b, y0 - 1 + rr, x0, t, va);
            sts_row(smem, y0 - 1 + rr, t, va);
        }
    }
    __syncthreads();

    // per-warp geometry: row r = wrp>>2, px0 = (wrp&3)*32
    const int r = wrp >> 2;
    const int px0 = (wrp & 3) * 32;

    // lane-invariant ldmatrix address pieces
    const uint32_t aLane = (uint32_t)((px0 + (lane & 15)) * A_XSTR + ((lane & 16) ? 16 : 0));
    const uint32_t bLane = sbase + OFF_WB +
                           (uint32_t)(((lane & 7) + ((lane & 16) ? 8 : 0)) * WB_STRIDE +
                                      ((lane & 8) ? 16 : 0));
    const int g = lane >> 2;
    const int tid4 = lane & 3;

    for (int y = y0; y < y0 + 32; y += 2) {
        // prefetch rows y+3, y+4 into registers (hidden under MMA)
        float va[17], vb[17];
        ldg_row(cen, b, y + 3, x0, t, va);
        ldg_row(cen, b, y + 4, x0, t, vb);

        float Cfr[2][4][4];
#pragma unroll
        for (int mt = 0; mt < 2; mt++)
#pragma unroll
            for (int nt = 0; nt < 4; nt++)
#pragma unroll
                for (int q = 0; q < 4; q++) Cfr[mt][nt][q] = 0.f;

        const int yr = y + r;
#pragma unroll
        for (int kh = 0; kh < 3; kh++) {
            const uint32_t aRing = sbase + ((yr - 1 + kh + 6) % 6) * A_SLOT + aLane;
#pragma unroll
            for (int kw = 0; kw < 3; kw++) {
                const int pos = kh * 3 + kw;
                const uint32_t aBase = aRing + kw * A_XSTR;
                const uint32_t bBase = bLane + pos * 64;
#pragma unroll
                for (int cih = 0; cih < 2; cih++) {
                    uint32_t Ah[2][4], Bh[8];
                    const uint32_t aOff = aBase + cih * 32;
#pragma unroll
                    for (int mt = 0; mt < 2; mt++)
                        ldsm_x4(aOff + mt * (16 * A_XSTR), Ah[mt][0], Ah[mt][1],
                                Ah[mt][2], Ah[mt][3]);
                    const uint32_t bOff = bBase + cih * 32;
                    ldsm_x4(bOff, Bh[0], Bh[1], Bh[2], Bh[3]);
                    ldsm_x4(bOff + 16 * WB_STRIDE, Bh[4], Bh[5], Bh[6], Bh[7]);
#pragma unroll
                    for (int mt = 0; mt < 2; mt++)
#pragma unroll
                        for (int nt = 0; nt < 4; nt++)
                            mma_f16(Cfr[mt][nt], Ah[mt], Bh[nt * 2], Bh[nt * 2 + 1]);
                }
            }
        }

        // commit prefetched rows BEFORE the barrier (slots y+3,y+4 are
        // disjoint from this iter's read slots y-1..y+2 among 6 residues)
        sts_row(smem, y + 3, t, va);
        sts_row(smem, y + 4, t, vb);
        __syncthreads();

        // epilogue AFTER the barrier: bias + SiLU + 1x1 dot, quad-lane reduce
        const float b1v = b1S[0];
#pragma unroll
        for (int mt = 0; mt < 2; mt++) {
            float sA = 0.f, sB = 0.f;
#pragma unroll
            for (int nt = 0; nt < 4; nt++) {
                int co0 = nt * 8 + 2 * tid4;
                float bs0 = biasS[co0], bs1 = biasS[co0 + 1];
                float w10 = w1S[co0], w11 = w1S[co0 + 1];
                float v0 = Cfr[mt][nt][0] + bs0;
                float v1 = Cfr[mt][nt][1] + bs1;
                float v2 = Cfr[mt][nt][2] + bs0;
                float v3 = Cfr[mt][nt][3] + bs1;
                sA = fmaf(w10, silu_fast(v0), sA);
                sA = fmaf(w11, silu_fast(v1), sA);
                sB = fmaf(w10, silu_fast(v2), sB);
                sB = fmaf(w11, silu_fast(v3), sB);
            }
            sA += __shfl_xor_sync(0xFFFFFFFF, sA, 1);
            sA += __shfl_xor_sync(0xFFFFFFFF, sA, 2);
            sB += __shfl_xor_sync(0xFFFFFFFF, sB, 1);
            sB += __shfl_xor_sync(0xFFFFFFFF, sB, 2);
            if (tid4 == 0) {
                int px = px0 + mt * 16;
                float* gp = &g_x[((size_t)b * H + yr) * W + x0 + px];
                gp[g] = sA + b1v;
                gp[g + 8] = sB + b1v;
            }
        }
    }
}

// ---- K2: shifted-difference attention + gate all channels (2 rows/block) ----
__device__ __forceinline__ float ldx(const float* __restrict__ X, int i, int j) {
    if ((unsigned)i < (unsigned)H && (unsigned)j < (unsigned)W)
        return __ldg(X + i * W + j);
    return 0.f;
}

__global__ __launch_bounds__(256) void stage2_kernel(
    const float* __restrict__ cen, float* __restrict__ out) {
    const int i = blockIdx.x * 2 + (threadIdx.x >> 7);
    const int b = blockIdx.y;
    const int j0 = (threadIdx.x & 127) * 4;
    const float* X = g_x + (size_t)b * H * W;

    float4 av;
    float* avp = (float*)&av;
#pragma unroll
    for (int p = 0; p < 4; p++) {
        int j = j0 + p;
        float x0 = X[i * W + j];
        float ms[2];
#pragma unroll
        for (int si = 0; si < 2; si++) {
            int s = si ? 3 : 1;
            float p0 = (x0 - ldx(X, i - s, j - s)) * (x0 - ldx(X, i + s, j + s));
            float p1 = (x0 - ldx(X, i - s, j)) * (x0 - ldx(X, i + s, j));
            float p2 = (x0 - ldx(X, i - s, j + s)) * (x0 - ldx(X, i + s, j - s));
            float p3 = (x0 - ldx(X, i, j - s)) * (x0 - ldx(X, i, j + s));
            ms[si] = fminf(fminf(p0, p1), fminf(p2, p3));
        }
        float att_in = (fmaxf(ms[0], ms[1]) + 0.5f * (ms[0] + ms[1])) * 0.5f;
        float rr = fmaxf(att_in, 0.f);
        avp[p] = 1.f / (1.f + __expf(-rr));
    }

    size_t base = ((size_t)b * C * H + i) * W + j0;
#pragma unroll
    for (int c = 0; c < C; c++) {
        const float4 v = *(const float4*)(cen + base + (size_t)c * H * W);
        float4 o;
        o.x = v.x * av.x;
        o.y = v.y * av.y;
        o.z = v.z * av.z;
        o.w = v.w * av.w;
        *(float4*)(out + base + (size_t)c * H * W) = o;
    }
}

extern "C" void kernel_launch(void* const* d_in, const int* in_sizes, int n_in,
                              void* d_out, int out_size) {
    const float* cen = (const float*)d_in[0];
    const float* w_conv = (const float*)d_in[1];
    const float* gamma = (const float*)d_in[2];
    const float* beta = (const float*)d_in[3];
    const float* mean = (const float*)d_in[4];
    const float* var = (const float*)d_in[5];
    const float* w1x1 = (const float*)d_in[6];
    const float* b1x1 = (const float*)d_in[7];
    float* out = (float*)d_out;

    cudaFuncSetAttribute(stage1_kernel, cudaFuncAttributeMaxDynamicSharedMemorySize,
                         SMEM_TOTAL);

    stage1_kernel<<<dim3(4, 16, BATCH), 256, SMEM_TOTAL>>>(cen, w_conv, gamma, beta,
                                                           mean, var, w1x1, b1x1);
    stage2_kernel<<<dim3(H / 2, BATCH), 256>>>(cen, out);
}